// round 6
// baseline (speedup 1.0000x reference)
#include <cuda_runtime.h>
#include <cuda_fp16.h>

// WarpingLayer v6: fp16 NHWC intermediate + fp16 conflict-free smem staging,
// 2-stage batch-half pipeline (transpose of second half overlaps gather of
// first half on a side stream; each launch is 4096 blocks -> chip stays full).
// Mask arithmetic reproduces the JAX reference fp32 op ordering exactly.

namespace {

constexpr int B = 8;
constexpr int C = 128;
constexpr int H = 128;
constexpr int W = 256;
constexpr int HW = H * W;                     // 32768
constexpr int BH = 4;                         // batches per pipeline stage

// 67 MB fp16 scratch for the transposed image (__device__ global: allowed).
__device__ __half g_xt[(size_t)B * HW * C];

// ---------------- Pass 1: NCHW f32 -> NHWC f16 (per batch-half) ----------------
__global__ __launch_bounds__(256) void transpose_kernel(const float* __restrict__ x,
                                                        int b_base)
{
    __shared__ float tile[32][133];
    const int hw0 = blockIdx.x * 128;
    const int c0  = blockIdx.y * 32;
    const int b   = b_base + blockIdx.z;
    const int tx  = threadIdx.x & 31;
    const int ty  = threadIdx.x >> 5;          // 0..7

    const float* px = x + (size_t)b * C * HW;
    #pragma unroll
    for (int i = 0; i < 4; ++i) {
        const int cl = ty + i * 8;             // 0..31
        const float4 v = __ldcs((const float4*)(px + (size_t)(c0 + cl) * HW + hw0) + tx);
        float* t = &tile[cl][4 * tx];
        t[0] = v.x; t[1] = v.y; t[2] = v.z; t[3] = v.w;
    }
    __syncthreads();

    __half* pt = g_xt + (size_t)b * HW * C;
    const int cpair = tx & 15;                 // channel pair 0..15
    const int hwsub = tx >> 4;                 // 0..1
    #pragma unroll
    for (int i = 0; i < 8; ++i) {
        const int hwl = (i * 8 + ty) * 2 + hwsub;          // 0..127
        const __half2 hv = __floats2half2_rn(tile[cpair * 2][hwl],
                                             tile[cpair * 2 + 1][hwl]);
        *(__half2*)(pt + (size_t)(hw0 + hwl) * C + c0 + cpair * 2) = hv;
    }
}

// ---------------- Pass 2: gather + write-back (per batch-half) ----------------
// Block = 8 warps = 32 pixels (same b,h). Warp computes 4 pixels; params in
// lanes 0..3, shfl-broadcast. Lane l handles channels {2l,2l+1, 64+2l,65+2l}
// (two half2 loads per corner). Staging tile: fp16, row stride 65 half2-words:
//   store  word 65p+l and 65p+32+l  -> 32 distinct banks (conflict-free)
//   load   word 65p+(c>>1)          -> bank p             (conflict-free)
__global__ __launch_bounds__(256) void warp_gather_kernel(
    const float* __restrict__ flow,
    float* __restrict__ out,
    int b_base)
{
    __shared__ __half2 tile[32 * 65];          // 8320 B

    const int tid  = threadIdx.x;
    const int warp = tid >> 5;
    const int lane = tid & 31;

    const int pix = ((int)gridDim.x - 1 - (int)blockIdx.x) * 32;  // reversed
    const int b  = b_base + (pix >> 15);
    const int h  = (pix >> 8) & (H - 1);
    const int w0 = pix & (W - 1);

    const __half* xt = g_xt + (size_t)b * HW * C;

    // ---- per-pixel params, computed in lanes 0..3 only ----
    float m00 = 0.f, m01 = 0.f, m10 = 0.f, m11 = 0.f, ones_val = 0.f;
    int o00 = 0, o01 = 0, o10 = 0, o11 = 0;
    if (lane < 4) {
        const int w = w0 + warp * 4 + lane;
        const int fbase = b * 2 * HW + h * W + w;
        const float fx = __ldg(flow + fbase);
        const float fy = __ldg(flow + fbase + HW);

        // Reference-exact fp32 ordering:
        const float flo_w = __fmul_rn(__fdiv_rn(__fmul_rn(fx, 2.0f), (float)(W - 1)), 1.0f);
        const float flo_h = __fmul_rn(__fdiv_rn(__fmul_rn(fy, 2.0f), (float)(H - 1)), 1.0f);
        const float step_x = __fdiv_rn(2.0f, (float)(W - 1));
        const float step_y = __fdiv_rn(2.0f, (float)(H - 1));
        const float gx = __fadd_rn(-1.0f, __fmul_rn((float)w, step_x));
        const float gy = __fadd_rn(-1.0f, __fmul_rn((float)h, step_y));

        const float ix = __fmul_rn(__fmul_rn(__fadd_rn(__fadd_rn(gx, flo_w), 1.0f), 0.5f), (float)(W - 1));
        const float iy = __fmul_rn(__fmul_rn(__fadd_rn(__fadd_rn(gy, flo_h), 1.0f), 0.5f), (float)(H - 1));

        const float x0f = floorf(ix);
        const float y0f = floorf(iy);
        const float x1f = __fadd_rn(x0f, 1.0f);
        const float y1f = __fadd_rn(y0f, 1.0f);

        const float wx1 = __fadd_rn(ix, -x0f);
        const float wx0 = __fadd_rn(1.0f, -wx1);
        const float wy1 = __fadd_rn(iy, -y0f);
        const float wy0 = __fadd_rn(1.0f, -wy1);

        const bool vx0 = (x0f >= 0.0f) && (x0f <= (float)(W - 1));
        const bool vx1 = (x1f >= 0.0f) && (x1f <= (float)(W - 1));
        const bool vy0 = (y0f >= 0.0f) && (y0f <= (float)(H - 1));
        const bool vy1 = (y1f >= 0.0f) && (y1f <= (float)(H - 1));

        m00 = (vx0 && vy0) ? __fmul_rn(wx0, wy0) : 0.0f;
        m01 = (vx1 && vy0) ? __fmul_rn(wx1, wy0) : 0.0f;
        m10 = (vx0 && vy1) ? __fmul_rn(wx0, wy1) : 0.0f;
        m11 = (vx1 && vy1) ? __fmul_rn(wx1, wy1) : 0.0f;
        ones_val = __fadd_rn(__fadd_rn(__fadd_rn(m00, m01), m10), m11);

        const int xi0 = min(max((int)x0f, 0), W - 1);
        const int xi1 = min(max((int)x1f, 0), W - 1);
        const int yi0 = min(max((int)y0f, 0), H - 1);
        const int yi1 = min(max((int)y1f, 0), H - 1);
        o00 = yi0 * W + xi0;
        o01 = yi0 * W + xi1;
        o10 = yi1 * W + xi0;
        o11 = yi1 * W + xi1;
    }

    const int cA = 2 * lane;           // channels 2l, 2l+1
    const int cB = 64 + 2 * lane;      // channels 64+2l, 65+2l

    #pragma unroll
    for (int pp = 0; pp < 4; ++pp) {
        const float ov = __shfl_sync(0xffffffffu, ones_val, pp);
        const int p = warp * 4 + pp;
        __half2 hA, hB;
        if (ov < 0.99999f) {
            hA = __float2half2_rn(0.0f);
            hB = hA;
        } else {
            const float w00 = __shfl_sync(0xffffffffu, m00, pp);
            const float w01 = __shfl_sync(0xffffffffu, m01, pp);
            const float w10 = __shfl_sync(0xffffffffu, m10, pp);
            const float w11 = __shfl_sync(0xffffffffu, m11, pp);
            const int   a00 = __shfl_sync(0xffffffffu, o00, pp);
            const int   a01 = __shfl_sync(0xffffffffu, o01, pp);
            const int   a10 = __shfl_sync(0xffffffffu, o10, pp);
            const int   a11 = __shfl_sync(0xffffffffu, o11, pp);

            const __half* r00 = xt + (size_t)a00 * C;
            const __half* r01 = xt + (size_t)a01 * C;
            const __half* r10 = xt + (size_t)a10 * C;
            const __half* r11 = xt + (size_t)a11 * C;

            const float2 f00a = __half22float2(*(const __half2*)(r00 + cA));
            const float2 f01a = __half22float2(*(const __half2*)(r01 + cA));
            const float2 f10a = __half22float2(*(const __half2*)(r10 + cA));
            const float2 f11a = __half22float2(*(const __half2*)(r11 + cA));
            const float2 f00b = __half22float2(*(const __half2*)(r00 + cB));
            const float2 f01b = __half22float2(*(const __half2*)(r01 + cB));
            const float2 f10b = __half22float2(*(const __half2*)(r10 + cB));
            const float2 f11b = __half22float2(*(const __half2*)(r11 + cB));

            const float v0 = fmaf(f11a.x, w11, fmaf(f10a.x, w10, fmaf(f01a.x, w01, f00a.x * w00)));
            const float v1 = fmaf(f11a.y, w11, fmaf(f10a.y, w10, fmaf(f01a.y, w01, f00a.y * w00)));
            const float v2 = fmaf(f11b.x, w11, fmaf(f10b.x, w10, fmaf(f01b.x, w01, f00b.x * w00)));
            const float v3 = fmaf(f11b.y, w11, fmaf(f10b.y, w10, fmaf(f01b.y, w01, f00b.y * w00)));

            hA = __floats2half2_rn(v0, v1);
            hB = __floats2half2_rn(v2, v3);
        }
        tile[65 * p + lane]      = hA;         // banks: all 32, conflict-free
        tile[65 * p + 32 + lane] = hB;
    }

    __syncthreads();

    // NCHW write-back: warp = fixed channel, lanes = consecutive w (coalesced).
    const int p  = tid & 31;
    const int c0 = tid >> 5;
    const __half* th = (const __half*)tile;
    float* po = out + (size_t)b * C * HW + (size_t)h * W + w0 + p;
    #pragma unroll
    for (int i = 0; i < 16; ++i) {
        const int c = c0 + i * 8;
        const __half hv = th[130 * p + c];     // word 65p + c/2 -> bank p
        __stcs(po + (size_t)c * HW, __half2float(hv));
    }
}

}  // namespace

extern "C" void kernel_launch(void* const* d_in, const int* in_sizes, int n_in,
                              void* d_out, int out_size) {
    const float* x    = (const float*)d_in[0];
    const float* flow = (const float*)d_in[1];
    float* out        = (float*)d_out;

    // One-time stream/event creation (no device-memory allocation involved).
    // Identical topology every call -> deterministic, graph-capturable fork/join.
    static bool s_init = false;
    static cudaStream_t s_side;
    static cudaEvent_t s_evRoot, s_evT0, s_evT1;
    if (!s_init) {
        cudaStreamCreateWithFlags(&s_side, cudaStreamNonBlocking);
        cudaEventCreateWithFlags(&s_evRoot, cudaEventDisableTiming);
        cudaEventCreateWithFlags(&s_evT0, cudaEventDisableTiming);
        cudaEventCreateWithFlags(&s_evT1, cudaEventDisableTiming);
        s_init = true;
    }

    dim3 tgrid(HW / 128, C / 32, BH);          // 4096 blocks per half
    const int gblocks = BH * HW / 32;          // 4096 blocks per half

    // Fork side stream off the main (capture) stream.
    cudaEventRecord(s_evRoot, 0);
    cudaStreamWaitEvent(s_side, s_evRoot, 0);

    transpose_kernel<<<tgrid, 256, 0, s_side>>>(x, 0);
    cudaEventRecord(s_evT0, s_side);
    transpose_kernel<<<tgrid, 256, 0, s_side>>>(x, BH);
    cudaEventRecord(s_evT1, s_side);

    cudaStreamWaitEvent(0, s_evT0, 0);
    warp_gather_kernel<<<gblocks, 256>>>(flow, out, 0);   // overlaps 2nd transpose
    cudaStreamWaitEvent(0, s_evT1, 0);
    warp_gather_kernel<<<gblocks, 256>>>(flow, out, BH);
    // Side-stream work is upstream of the last gather -> streams joined.
}